// round 13
// baseline (speedup 1.0000x reference)
#include <cuda_runtime.h>
#include <cuda_bf16.h>
#include <math.h>
#include <stdint.h>

#define B_   2
#define L_   1024
#define DM   2048
#define DI   4096
#define DS   16
#define DTR  128
#define T_   (B_*L_)        // 2048 tokens (power of 2: T_=2048=1<<11)
#define NX   160            // dt_rank + 2*d_state
#define NXPAD 256
#define KSPLITS 8

// ---------------- scratch (static __device__ arrays; no allocation) ----------------
// ALL activation matrices stored k-major (transposed): X_t[feature][token]
__device__ float g_hsT  [(size_t)DM*T_];
__device__ float g_xzT  [(size_t)2*DI*T_];
__device__ float g_xcT  [(size_t)DI*T_];
__device__ float g_xdblp[(size_t)KSPLITS*NXPAD*T_];
__device__ float g_xdblT[(size_t)NX*T_];
__device__ float g_dtT  [(size_t)DI*T_];
__device__ float g_ysT  [(size_t)DI*T_];
// transposed (k-major) weights
__device__ float g_wipT [(size_t)DM*2*DI];     // [2048][8192]
__device__ float g_wxpT [(size_t)DI*NXPAD];    // [4096][256] zero-padded
__device__ float g_wdtT [(size_t)DTR*DI];      // [128][4096]
__device__ float g_wopT [(size_t)DI*DM];       // [4096][2048]

// ---------------- helpers ----------------
__device__ __forceinline__ float siluf(float x) { return x / (1.0f + expf(-x)); }
__device__ __forceinline__ float softplusf(float x) { return (x > 20.0f) ? x : log1pf(expf(x)); }

typedef unsigned long long u64;

__device__ __forceinline__ u64 fma2(u64 a, u64 b, u64 c) {
    u64 d;
    asm("fma.rn.f32x2 %0, %1, %2, %3;" : "=l"(d) : "l"(a), "l"(b), "l"(c));
    return d;
}
__device__ __forceinline__ u64 dup2(float x) {
    u64 d;
    asm("mov.b64 %0, {%1, %1};" : "=l"(d) : "f"(x));
    return d;
}
__device__ __forceinline__ float2 unpk(u64 v) {
    float2 f;
    asm("mov.b64 {%0, %1}, %2;" : "=f"(f.x), "=f"(f.y) : "l"(v));
    return f;
}
__device__ __forceinline__ uint32_t smaddr(const void* p) {
    return (uint32_t)__cvta_generic_to_shared(p);
}
__device__ __forceinline__ void cpasync16(uint32_t dst, const float* src) {
    asm volatile("cp.async.cg.shared.global [%0], [%1], 16;\n" :: "r"(dst), "l"(src));
}

// ---------------- weight transpose: in[nin][kin] -> out[kin][nout], rows n>=nin zero ----
__global__ void wtrans(const float* __restrict__ in, float* __restrict__ out,
                       int nin, int kin, int nout) {
    __shared__ float t[32][33];
    int k0 = blockIdx.x * 32, n0 = blockIdx.y * 32;
    int tx = threadIdx.x, ty = threadIdx.y;   // 32 x 8
#pragma unroll
    for (int i = 0; i < 32; i += 8) {
        int n = n0 + ty + i;
        t[ty + i][tx] = (n < nin) ? in[(size_t)n * kin + k0 + tx] : 0.f;
    }
    __syncthreads();
#pragma unroll
    for (int i = 0; i < 32; i += 8) {
        int k = k0 + ty + i;
        out[(size_t)k * nout + n0 + tx] = t[tx][ty + i];
    }
}

// ---------------- 1) fused add + RMSNorm -> hsT (k-major) ----------------
__global__ void addnorm_kernel(const float* __restrict__ h, const float* __restrict__ r,
                               const float* __restrict__ w, float* __restrict__ resid_out,
                               float* __restrict__ hsT) {
    int t = blockIdx.x;
    int tid = threadIdx.x;
    const float* hp = h + (size_t)t * DM;
    const float* rp = r + (size_t)t * DM;
    float v[8];
    float ss = 0.f;
#pragma unroll
    for (int i = 0; i < 8; i++) {
        int c = tid + i * 256;
        float x = hp[c] + rp[c];
        v[i] = x;
        ss += x * x;
    }
    __shared__ float red[256];
    red[tid] = ss;
    __syncthreads();
    for (int s = 128; s > 0; s >>= 1) {
        if (tid < s) red[tid] += red[tid + s];
        __syncthreads();
    }
    float scale = rsqrtf(red[0] / (float)DM + 1e-5f);
#pragma unroll
    for (int i = 0; i < 8; i++) {
        int c = tid + i * 256;
        if (resid_out) resid_out[(size_t)t * DM + c] = v[i];
        hsT[(size_t)c * T_ + t] = v[i] * scale * w[c];
    }
}

// ---------------- 2) cp.async 3-stage SGEMM, all operands k-major ----------------
// C[M,N] = A[M,K]*W[N,K]^T with At[k][m], Wt[k][n] in global (k-major).
// 128x128 CTA tile, BK=16, 256 threads, 8x8/thread (f32x2 pairs along N).
// CT==1: write C transposed Ct[n][m] (ldc = row stride of Ct). EPI==1: softplus+bias.
template<int EPI, int CT>
__global__ void __launch_bounds__(256, 2)
sgemm_ca(const float* __restrict__ At, const float* __restrict__ Wt, float* __restrict__ C,
         int ldat, int ldwt, int ldc, int klen, long slab, const float* __restrict__ bias) {
    __shared__ float As[3][16][128];
    __shared__ float Ws[3][16][128];
    int tid = threadIdx.x;
    int m0 = blockIdx.y * 128, n0 = blockIdx.x * 128;
    int kstart = blockIdx.z * klen;
    float* Cb = C + (size_t)blockIdx.z * slab;

    // cp.async mapping: thread -> 2 chunks per tile; kk = tid>>4, chunk col = (tid&15)*8
    int kkc = tid >> 4;
    int cc = (tid & 15) * 8;      // float offset of first chunk
    uint32_t dA[3], dW[3];
#pragma unroll
    for (int b = 0; b < 3; b++) {
        dA[b] = smaddr(&As[b][kkc][cc]);
        dW[b] = smaddr(&Ws[b][kkc][cc]);
    }
    const float* srcA = At + (size_t)(kstart + kkc) * ldat + m0 + cc;
    const float* srcW = Wt + (size_t)(kstart + kkc) * ldwt + n0 + cc;

    int tx = tid & 15, ty = tid >> 4;
    int nst = klen >> 4;

    u64 acc[2][4][4];
#pragma unroll
    for (int rh = 0; rh < 2; rh++)
#pragma unroll
        for (int i = 0; i < 4; i++)
#pragma unroll
            for (int j = 0; j < 4; j++) acc[rh][i][j] = 0ull;

    // prologue: stages 0 and 1
#pragma unroll
    for (int p = 0; p < 2; p++) {
        cpasync16(dA[p], srcA);
        cpasync16(dA[p] + 16, srcA + 4);
        cpasync16(dW[p], srcW);
        cpasync16(dW[p] + 16, srcW + 4);
        asm volatile("cp.async.commit_group;\n");
        srcA += (size_t)16 * ldat;
        srcW += (size_t)16 * ldwt;
    }

    for (int s = 0; s < nst; s++) {
        int buf = s - (s / 3) * 3;
        asm volatile("cp.async.wait_group 1;\n");
        __syncthreads();
        // issue stage s+2 into buffer (s+2)%3 (safe: all threads past barrier => done with stage s-1)
        if (s + 2 < nst) {
            int b2 = buf + 2; if (b2 >= 3) b2 -= 3;
            cpasync16(dA[b2], srcA);
            cpasync16(dA[b2] + 16, srcA + 4);
            cpasync16(dW[b2], srcW);
            cpasync16(dW[b2] + 16, srcW + 4);
            srcA += (size_t)16 * ldat;
            srcW += (size_t)16 * ldwt;
        }
        asm volatile("cp.async.commit_group;\n");
#pragma unroll
        for (int kk = 0; kk < 16; kk++) {
            float4 a0 = *(const float4*)&As[buf][kk][ty * 4];
            float4 a1 = *(const float4*)&As[buf][kk][64 + ty * 4];
            ulonglong2 b0 = *(const ulonglong2*)&Ws[buf][kk][tx * 4];
            ulonglong2 b1 = *(const ulonglong2*)&Ws[buf][kk][64 + tx * 4];
            u64 d;
            d = dup2(a0.x);
            acc[0][0][0] = fma2(d, b0.x, acc[0][0][0]);
            acc[0][0][1] = fma2(d, b0.y, acc[0][0][1]);
            acc[0][0][2] = fma2(d, b1.x, acc[0][0][2]);
            acc[0][0][3] = fma2(d, b1.y, acc[0][0][3]);
            d = dup2(a0.y);
            acc[0][1][0] = fma2(d, b0.x, acc[0][1][0]);
            acc[0][1][1] = fma2(d, b0.y, acc[0][1][1]);
            acc[0][1][2] = fma2(d, b1.x, acc[0][1][2]);
            acc[0][1][3] = fma2(d, b1.y, acc[0][1][3]);
            d = dup2(a0.z);
            acc[0][2][0] = fma2(d, b0.x, acc[0][2][0]);
            acc[0][2][1] = fma2(d, b0.y, acc[0][2][1]);
            acc[0][2][2] = fma2(d, b1.x, acc[0][2][2]);
            acc[0][2][3] = fma2(d, b1.y, acc[0][2][3]);
            d = dup2(a0.w);
            acc[0][3][0] = fma2(d, b0.x, acc[0][3][0]);
            acc[0][3][1] = fma2(d, b0.y, acc[0][3][1]);
            acc[0][3][2] = fma2(d, b1.x, acc[0][3][2]);
            acc[0][3][3] = fma2(d, b1.y, acc[0][3][3]);
            d = dup2(a1.x);
            acc[1][0][0] = fma2(d, b0.x, acc[1][0][0]);
            acc[1][0][1] = fma2(d, b0.y, acc[1][0][1]);
            acc[1][0][2] = fma2(d, b1.x, acc[1][0][2]);
            acc[1][0][3] = fma2(d, b1.y, acc[1][0][3]);
            d = dup2(a1.y);
            acc[1][1][0] = fma2(d, b0.x, acc[1][1][0]);
            acc[1][1][1] = fma2(d, b0.y, acc[1][1][1]);
            acc[1][1][2] = fma2(d, b1.x, acc[1][1][2]);
            acc[1][1][3] = fma2(d, b1.y, acc[1][1][3]);
            d = dup2(a1.z);
            acc[1][2][0] = fma2(d, b0.x, acc[1][2][0]);
            acc[1][2][1] = fma2(d, b0.y, acc[1][2][1]);
            acc[1][2][2] = fma2(d, b1.x, acc[1][2][2]);
            acc[1][2][3] = fma2(d, b1.y, acc[1][2][3]);
            d = dup2(a1.w);
            acc[1][3][0] = fma2(d, b0.x, acc[1][3][0]);
            acc[1][3][1] = fma2(d, b0.y, acc[1][3][1]);
            acc[1][3][2] = fma2(d, b1.x, acc[1][3][2]);
            acc[1][3][3] = fma2(d, b1.y, acc[1][3][3]);
        }
    }

    if (CT) {
        // transposed epilogue: Ct[n][m]
#pragma unroll
        for (int q = 0; q < 4; q++) {
#pragma unroll
            for (int lane = 0; lane < 2; lane++) {
                int col = n0 + (q >> 1) * 64 + tx * 4 + (q & 1) * 2 + lane;
                float bv = (EPI == 1) ? bias[col] : 0.f;
#pragma unroll
                for (int rh = 0; rh < 2; rh++) {
                    int m = m0 + rh * 64 + ty * 4;
                    float2 f0 = unpk(acc[rh][0][q]);
                    float2 f1 = unpk(acc[rh][1][q]);
                    float2 f2 = unpk(acc[rh][2][q]);
                    float2 f3 = unpk(acc[rh][3][q]);
                    float v0 = lane ? f0.y : f0.x;
                    float v1 = lane ? f1.y : f1.x;
                    float v2 = lane ? f2.y : f2.x;
                    float v3 = lane ? f3.y : f3.x;
                    if (EPI == 1) {
                        v0 = softplusf(v0 + bv); v1 = softplusf(v1 + bv);
                        v2 = softplusf(v2 + bv); v3 = softplusf(v3 + bv);
                    }
                    *(float4*)&Cb[(size_t)col * ldc + m] = make_float4(v0, v1, v2, v3);
                }
            }
        }
    } else {
        // row-major epilogue: C[m][n]
#pragma unroll
        for (int rh = 0; rh < 2; rh++)
#pragma unroll
            for (int i = 0; i < 4; i++) {
                int row = m0 + rh * 64 + ty * 4 + i;
#pragma unroll
                for (int ch = 0; ch < 2; ch++) {
                    int col = n0 + ch * 64 + tx * 4;
                    float2 lo = unpk(acc[rh][i][ch * 2 + 0]);
                    float2 hi = unpk(acc[rh][i][ch * 2 + 1]);
                    float v0 = lo.x, v1 = lo.y, v2 = hi.x, v3 = hi.y;
                    if (EPI == 1) {
                        v0 = softplusf(v0 + bias[col + 0]);
                        v1 = softplusf(v1 + bias[col + 1]);
                        v2 = softplusf(v2 + bias[col + 2]);
                        v3 = softplusf(v3 + bias[col + 3]);
                    }
                    *(float4*)&Cb[(size_t)row * ldc + col] = make_float4(v0, v1, v2, v3);
                }
            }
    }
}

// ---------------- 3) depthwise causal conv + SiLU (xzT -> xcT, both k-major) ----------
__global__ void conv_silu_kernel(const float* __restrict__ xzT,
                                 const float* __restrict__ cw,
                                 const float* __restrict__ cb,
                                 float* __restrict__ xcT) {
    int d = blockIdx.x * 256 + threadIdx.x;
    int b = blockIdx.z;
    int l0 = blockIdx.y * 64;
    float c0 = cw[d * 4 + 0], c1 = cw[d * 4 + 1], c2 = cw[d * 4 + 2], c3 = cw[d * 4 + 3];
    float bias = cb[d];
    const float* xrow = xzT + (size_t)d * T_ + b * L_;
    float* orow = xcT + (size_t)d * T_ + b * L_;
    float w0 = (l0 >= 3) ? xrow[l0 - 3] : 0.f;
    float w1 = (l0 >= 2) ? xrow[l0 - 2] : 0.f;
    float w2 = (l0 >= 1) ? xrow[l0 - 1] : 0.f;
    for (int i = 0; i < 64; i++) {
        int l = l0 + i;
        float xv = xrow[l];
        float a = bias + c0 * w0 + c1 * w1 + c2 * w2 + c3 * xv;
        orow[l] = siluf(a);
        w0 = w1; w1 = w2; w2 = xv;
    }
}

// ---------------- 4) split-K reduce (partials -> xdblT) ----------------
__global__ void xdbl_reduce_kernel(const float* __restrict__ part, float* __restrict__ outT) {
    int idx = blockIdx.x * 256 + threadIdx.x;   // over NX*T_ (n-major)
    if (idx >= NX * T_) return;
    float s = 0.f;
#pragma unroll
    for (int z = 0; z < KSPLITS; z++)
        s += part[(size_t)z * NXPAD * T_ + idx];
    outT[idx] = s;
}

// ---------------- 5) selective scan (k-major inputs/outputs) ----------------
__global__ void scan_kernel(const float* __restrict__ dtT, const float* __restrict__ xcT,
                            const float* __restrict__ xdblT, const float* __restrict__ A_log,
                            float* __restrict__ ysT) {
    int tid = threadIdx.x;
    int lane = tid & 15;
    int grp = tid >> 4;
    int ch = blockIdx.x * 8 + grp;
    int b = ch >> 12;
    int d = ch & (DI - 1);
    float Aval = -expf(A_log[d * DS + lane]);
    float h = 0.f;
    const float* dtrow = dtT + (size_t)d * T_ + b * L_;
    const float* xcrow = xcT + (size_t)d * T_ + b * L_;
    const float* Brow = xdblT + (size_t)(DTR + lane) * T_ + b * L_;
    const float* Crow = xdblT + (size_t)(DTR + DS + lane) * T_ + b * L_;
    float* yrow = ysT + (size_t)d * T_ + b * L_;
    for (int l = 0; l < L_; l++) {
        float dtv = dtrow[l];
        float xv = xcrow[l];
        float dA = __expf(dtv * Aval);
        h = fmaf(dA, h, dtv * xv * Brow[l]);
        float yp = h * Crow[l];
        yp += __shfl_xor_sync(0xffffffffu, yp, 8);
        yp += __shfl_xor_sync(0xffffffffu, yp, 4);
        yp += __shfl_xor_sync(0xffffffffu, yp, 2);
        yp += __shfl_xor_sync(0xffffffffu, yp, 1);
        if (lane == 0) yrow[l] = yp;
    }
}

// ---------------- 6) gating (all k-major): ys = (ys + xc*D) * silu(z) ----------------
__global__ void gate_kernel(const float* __restrict__ xzT, const float* __restrict__ xcT,
                            const float* __restrict__ Dp, float* __restrict__ ysT) {
    size_t idx = (size_t)blockIdx.x * 256 + threadIdx.x;   // d*T_ + t
    int d = (int)(idx >> 11);
    float z = xzT[(size_t)(DI + d) * T_ + (idx & (T_ - 1))];
    ysT[idx] = (ysT[idx] + xcT[idx] * Dp[d]) * siluf(z);
}

// ---------------- launch ----------------
extern "C" void kernel_launch(void* const* d_in, const int* in_sizes, int n_in,
                              void* d_out, int out_size) {
    const float* hidden   = (const float*)d_in[0];
    const float* residual = (const float*)d_in[1];
    const float* norm_w   = (const float*)d_in[2];
    const float* in_proj  = (const float*)d_in[3];   // [8192, 2048]
    const float* conv_w   = (const float*)d_in[4];
    const float* conv_b   = (const float*)d_in[5];
    const float* x_proj   = (const float*)d_in[6];   // [160, 4096]
    const float* dt_proj  = (const float*)d_in[7];   // [4096, 128]
    const float* dt_bias  = (const float*)d_in[8];
    const float* A_log    = (const float*)d_in[9];
    const float* D_param  = (const float*)d_in[10];
    const float* out_proj = (const float*)d_in[11];  // [2048, 4096]

    float* out = (float*)d_out;
    float* resid_out = (out_size >= 2 * T_ * DM) ? out + (size_t)T_ * DM : nullptr;

    dim3 tb(32, 8);
    // weight transposes (k-major): out[kin][nout]
    wtrans<<<dim3(DM / 32, 2 * DI / 32), tb>>>(in_proj, g_wipT, 2 * DI, DM, 2 * DI);
    wtrans<<<dim3(DI / 32, NXPAD / 32), tb>>>(x_proj, g_wxpT, NX, DI, NXPAD);
    wtrans<<<dim3(DTR / 32, DI / 32), tb>>>(dt_proj, g_wdtT, DI, DTR, DI);
    wtrans<<<dim3(DI / 32, DM / 32), tb>>>(out_proj, g_wopT, DM, DI, DM);

    // 1) add + rmsnorm -> hsT
    addnorm_kernel<<<T_, 256>>>(hidden, residual, norm_w, resid_out, g_hsT);

    // 2) xzT = (hs @ in_proj^T)^T : M=2048, N=8192, K=2048
    sgemm_ca<0, 1><<<dim3(2 * DI / 128, T_ / 128, 1), 256>>>(
        g_hsT, g_wipT, g_xzT, T_, 2 * DI, T_, DM, 0, nullptr);

    // 3) conv + silu -> xcT
    conv_silu_kernel<<<dim3(DI / 256, L_ / 64, B_), 256>>>(g_xzT, conv_w, conv_b, g_xcT);

    // 4) x_dbl partials: M=2048, N=256(padded), K=4096, split-K=8
    sgemm_ca<0, 1><<<dim3(NXPAD / 128, T_ / 128, KSPLITS), 256>>>(
        g_xcT, g_wxpT, g_xdblp, T_, NXPAD, T_, DI / KSPLITS, (long)NXPAD * T_, nullptr);
    xdbl_reduce_kernel<<<(NX * T_ + 255) / 256, 256>>>(g_xdblp, g_xdblT);

    // 5) dtT = softplus((x_dbl @ dt_proj^T))^T : M=2048, N=4096, K=128
    sgemm_ca<1, 1><<<dim3(DI / 128, T_ / 128, 1), 256>>>(
        g_xdblT, g_wdtT, g_dtT, T_, DI, T_, DTR, 0, dt_bias);

    // 6) selective scan -> ysT
    scan_kernel<<<B_ * DI / 8, 128>>>(g_dtT, g_xcT, g_xdblT, A_log, g_ysT);

    // 7) gate (in place on ysT)
    gate_kernel<<<(int)(((size_t)T_ * DI) / 256), 256>>>(g_xzT, g_xcT, D_param, g_ysT);

    // 8) out = y @ out_proj^T (row-major output) : M=2048, N=2048, K=4096
    sgemm_ca<0, 0><<<dim3(DM / 128, T_ / 128, 1), 256>>>(
        g_ysT, g_wopT, out, T_, DM, DM, DI, 0, nullptr);
}

// round 16
// speedup vs baseline: 3.1676x; 3.1676x over previous
#include <cuda_runtime.h>
#include <cuda_bf16.h>
#include <math.h>
#include <stdint.h>

#define B_   2
#define L_   1024
#define DM   2048
#define DI   4096
#define DS   16
#define DTR  128
#define T_   (B_*L_)        // 2048 tokens
#define NX   160            // dt_rank + 2*d_state
#define NXPAD 256
#define KSPLITS 8

// ---------------- scratch (static __device__ arrays; no allocation) ----------------
__device__ float g_hs   [(size_t)T_*DM];
__device__ float g_xz   [(size_t)T_*2*DI];
__device__ float g_xc   [(size_t)T_*DI];
__device__ float g_xdblp[(size_t)KSPLITS*T_*NXPAD];
__device__ float g_xdbl [(size_t)T_*NX];
__device__ float g_dt   [(size_t)T_*DI];
__device__ float g_ys   [(size_t)T_*DI];

// ---------------- helpers ----------------
__device__ __forceinline__ float siluf(float x) { return x / (1.0f + expf(-x)); }
__device__ __forceinline__ float softplusf(float x) { return (x > 20.0f) ? x : log1pf(expf(x)); }

typedef unsigned long long u64;

__device__ __forceinline__ u64 fma2(u64 a, u64 b, u64 c) {
    u64 d;
    asm("fma.rn.f32x2 %0, %1, %2, %3;" : "=l"(d) : "l"(a), "l"(b), "l"(c));
    return d;
}
__device__ __forceinline__ u64 dup2(float x) {
    u64 d;
    asm("mov.b64 %0, {%1, %1};" : "=l"(d) : "f"(x));
    return d;
}
__device__ __forceinline__ float2 unpk(u64 v) {
    float2 f;
    asm("mov.b64 {%0, %1}, %2;" : "=f"(f.x), "=f"(f.y) : "l"(v));
    return f;
}

// ---------------- 1) fused add + RMSNorm ----------------
__global__ void addnorm_kernel(const float* __restrict__ h, const float* __restrict__ r,
                               const float* __restrict__ w, float* __restrict__ resid_out,
                               float* __restrict__ hs) {
    int t = blockIdx.x;
    int tid = threadIdx.x;
    const float* hp = h + (size_t)t * DM;
    const float* rp = r + (size_t)t * DM;
    float v[8];
    float ss = 0.f;
#pragma unroll
    for (int i = 0; i < 8; i++) {
        int c = tid + i * 256;
        float x = hp[c] + rp[c];
        v[i] = x;
        ss += x * x;
    }
    __shared__ float red[256];
    red[tid] = ss;
    __syncthreads();
    for (int s = 128; s > 0; s >>= 1) {
        if (tid < s) red[tid] += red[tid + s];
        __syncthreads();
    }
    float scale = rsqrtf(red[0] / (float)DM + 1e-5f);
#pragma unroll
    for (int i = 0; i < 8; i++) {
        int c = tid + i * 256;
        if (resid_out) resid_out[(size_t)t * DM + c] = v[i];
        hs[(size_t)t * DM + c] = v[i] * scale * w[c];
    }
}

// ---------------- 2) fp32 SGEMM with packed f32x2 FMA ----------------
// C[M,N] = A[M,K] * W[N,K]^T. 128x64 CTA tile, BK=16, 256 threads, 8x4/thread.
// Register-staged double buffering, ONE __syncthreads per stage, 3 CTAs/SM.
template<int EPI, bool NGUARD>
__global__ void __launch_bounds__(256, 3)
sgemm2(const float* __restrict__ A, const float* __restrict__ W, float* __restrict__ C,
       int M, int Nlog, int lda, int ldw, int ldc, int klen,
       const float* __restrict__ bias) {
    __shared__ float As[2][16][132];
    __shared__ float Ws[2][16][68];
    int tid = threadIdx.x;
    int m0 = blockIdx.y * 128, n0 = blockIdx.x * 64;
    int kstart = blockIdx.z * klen;
    float* Cb = C + (size_t)blockIdx.z * M * ldc;

    // A loader: 2 float4 per thread (row r, k-offset k8)
    int r = tid >> 1;
    int k8 = (tid & 1) * 8;
    const float* Ag = A + (size_t)(m0 + r) * lda + kstart + k8;
    // W loader: 1 float4 per thread (row rw, k-offset k4)
    int rw = tid & 63;
    int k4 = (tid >> 6) * 4;
    const float* Wg = W + (size_t)(n0 + rw) * ldw + kstart + k4;
    bool wvalid = true;
    if (NGUARD) wvalid = (n0 + rw) < Nlog;

    int tx = tid & 15, ty = tid >> 4;

    u64 acc[2][4][2];
#pragma unroll
    for (int rh = 0; rh < 2; rh++)
#pragma unroll
        for (int i = 0; i < 4; i++)
#pragma unroll
            for (int j = 0; j < 2; j++) acc[rh][i][j] = 0ull;

    float4 z4 = make_float4(0.f, 0.f, 0.f, 0.f);
    float4 pa0 = *(const float4*)Ag;
    float4 pa1 = *(const float4*)(Ag + 4);
    float4 pw0 = wvalid ? *(const float4*)Wg : z4;

    int nst = klen >> 4;

    As[0][k8 + 0][r] = pa0.x; As[0][k8 + 1][r] = pa0.y;
    As[0][k8 + 2][r] = pa0.z; As[0][k8 + 3][r] = pa0.w;
    As[0][k8 + 4][r] = pa1.x; As[0][k8 + 5][r] = pa1.y;
    As[0][k8 + 6][r] = pa1.z; As[0][k8 + 7][r] = pa1.w;
    Ws[0][k4 + 0][rw] = pw0.x; Ws[0][k4 + 1][rw] = pw0.y;
    Ws[0][k4 + 2][rw] = pw0.z; Ws[0][k4 + 3][rw] = pw0.w;
    if (nst > 1) {
        Ag += 16; Wg += 16;
        pa0 = *(const float4*)Ag;
        pa1 = *(const float4*)(Ag + 4);
        pw0 = wvalid ? *(const float4*)Wg : z4;
    }

    for (int s = 0; s < nst; s++) {
        int buf = s & 1;
        __syncthreads();
        if (s + 1 < nst) {
            int b2 = buf ^ 1;
            As[b2][k8 + 0][r] = pa0.x; As[b2][k8 + 1][r] = pa0.y;
            As[b2][k8 + 2][r] = pa0.z; As[b2][k8 + 3][r] = pa0.w;
            As[b2][k8 + 4][r] = pa1.x; As[b2][k8 + 5][r] = pa1.y;
            As[b2][k8 + 6][r] = pa1.z; As[b2][k8 + 7][r] = pa1.w;
            Ws[b2][k4 + 0][rw] = pw0.x; Ws[b2][k4 + 1][rw] = pw0.y;
            Ws[b2][k4 + 2][rw] = pw0.z; Ws[b2][k4 + 3][rw] = pw0.w;
            if (s + 2 < nst) {
                Ag += 16; Wg += 16;
                pa0 = *(const float4*)Ag;
                pa1 = *(const float4*)(Ag + 4);
                pw0 = wvalid ? *(const float4*)Wg : z4;
            }
        }
        // compute 16 k-steps on buf
#pragma unroll
        for (int kk = 0; kk < 16; kk++) {
            float4 a0 = *(const float4*)&As[buf][kk][ty * 4];
            float4 a1 = *(const float4*)&As[buf][kk][64 + ty * 4];
            ulonglong2 b0 = *(const ulonglong2*)&Ws[buf][kk][tx * 4];
            u64 d;
            d = dup2(a0.x);
            acc[0][0][0] = fma2(d, b0.x, acc[0][0][0]);
            acc[0][0][1] = fma2(d, b0.y, acc[0][0][1]);
            d = dup2(a0.y);
            acc[0][1][0] = fma2(d, b0.x, acc[0][1][0]);
            acc[0][1][1] = fma2(d, b0.y, acc[0][1][1]);
            d = dup2(a0.z);
            acc[0][2][0] = fma2(d, b0.x, acc[0][2][0]);
            acc[0][2][1] = fma2(d, b0.y, acc[0][2][1]);
            d = dup2(a0.w);
            acc[0][3][0] = fma2(d, b0.x, acc[0][3][0]);
            acc[0][3][1] = fma2(d, b0.y, acc[0][3][1]);
            d = dup2(a1.x);
            acc[1][0][0] = fma2(d, b0.x, acc[1][0][0]);
            acc[1][0][1] = fma2(d, b0.y, acc[1][0][1]);
            d = dup2(a1.y);
            acc[1][1][0] = fma2(d, b0.x, acc[1][1][0]);
            acc[1][1][1] = fma2(d, b0.y, acc[1][1][1]);
            d = dup2(a1.z);
            acc[1][2][0] = fma2(d, b0.x, acc[1][2][0]);
            acc[1][2][1] = fma2(d, b0.y, acc[1][2][1]);
            d = dup2(a1.w);
            acc[1][3][0] = fma2(d, b0.x, acc[1][3][0]);
            acc[1][3][1] = fma2(d, b0.y, acc[1][3][1]);
        }
    }

#pragma unroll
    for (int rh = 0; rh < 2; rh++)
#pragma unroll
        for (int i = 0; i < 4; i++) {
            int row = m0 + rh * 64 + ty * 4 + i;
            int col = n0 + tx * 4;
            float2 lo = unpk(acc[rh][i][0]);
            float2 hi = unpk(acc[rh][i][1]);
            float v0 = lo.x, v1 = lo.y, v2 = hi.x, v3 = hi.y;
            if (EPI == 1) {
                v0 = softplusf(v0 + bias[col + 0]);
                v1 = softplusf(v1 + bias[col + 1]);
                v2 = softplusf(v2 + bias[col + 2]);
                v3 = softplusf(v3 + bias[col + 3]);
            }
            *(float4*)&Cb[(size_t)row * ldc + col] = make_float4(v0, v1, v2, v3);
        }
}

// ---------------- 3) depthwise causal conv (width 4) + SiLU ----------------
__global__ void conv_silu_kernel(const float* __restrict__ xz,
                                 const float* __restrict__ cw,
                                 const float* __restrict__ cb,
                                 float* __restrict__ xc) {
    int d = blockIdx.x * 256 + threadIdx.x;
    int b = blockIdx.z;
    int l0 = blockIdx.y * 64;
    float c0 = cw[d * 4 + 0], c1 = cw[d * 4 + 1], c2 = cw[d * 4 + 2], c3 = cw[d * 4 + 3];
    float bias = cb[d];
    float w0 = 0.f, w1 = 0.f, w2 = 0.f;
#pragma unroll
    for (int j = 3; j >= 1; j--) {
        int l = l0 - j;
        float v = (l >= 0) ? xz[((size_t)(b * L_ + l)) * (2 * DI) + d] : 0.f;
        if (j == 3) w0 = v;
        else if (j == 2) w1 = v;
        else w2 = v;
    }
    for (int i = 0; i < 64; i++) {
        int l = l0 + i;
        float xv = xz[((size_t)(b * L_ + l)) * (2 * DI) + d];
        float a = bias + c0 * w0 + c1 * w1 + c2 * w2 + c3 * xv;
        xc[((size_t)(b * L_ + l)) * DI + d] = siluf(a);
        w0 = w1; w1 = w2; w2 = xv;
    }
}

// ---------------- 4) split-K reduce for x_dbl ----------------
__global__ void xdbl_reduce_kernel(const float* __restrict__ part, float* __restrict__ out) {
    int idx = blockIdx.x * 256 + threadIdx.x;
    if (idx >= T_ * NX) return;
    int t = idx / NX;
    int n = idx - t * NX;
    float s = 0.f;
#pragma unroll
    for (int z = 0; z < KSPLITS; z++)
        s += part[((size_t)z * T_ + t) * NXPAD + n];
    out[idx] = s;
}

// ---------------- 5) selective scan ----------------
__global__ void scan_kernel(const float* __restrict__ dt, const float* __restrict__ xc,
                            const float* __restrict__ xdbl, const float* __restrict__ A_log,
                            float* __restrict__ ys) {
    int tid = threadIdx.x;
    int lane = tid & 15;
    int grp = tid >> 4;
    int ch = blockIdx.x * 8 + grp;
    int b = ch >> 12;
    int d = ch & (DI - 1);
    float Aval = -expf(A_log[d * DS + lane]);
    float h = 0.f;
    size_t baseRow = (size_t)b * L_;
    for (int l = 0; l < L_; l++) {
        size_t t = baseRow + l;
        float dtv = dt[t * DI + d];
        float xv = xc[t * DI + d];
        const float* xd = xdbl + t * NX;
        float bs = xd[DTR + lane];
        float cs = xd[DTR + DS + lane];
        float dA = __expf(dtv * Aval);
        h = fmaf(dA, h, dtv * xv * bs);
        float yp = h * cs;
        yp += __shfl_xor_sync(0xffffffffu, yp, 8);
        yp += __shfl_xor_sync(0xffffffffu, yp, 4);
        yp += __shfl_xor_sync(0xffffffffu, yp, 2);
        yp += __shfl_xor_sync(0xffffffffu, yp, 1);
        if (lane == 0) ys[t * DI + d] = yp;
    }
}

// ---------------- 6) gating: y = (ys + xc*D) * silu(z) ----------------
__global__ void gate_kernel(const float* __restrict__ xz, const float* __restrict__ xc,
                            const float* __restrict__ Dp, float* __restrict__ ys) {
    size_t idx = (size_t)blockIdx.x * 256 + threadIdx.x;
    size_t t = idx / DI;
    int d = (int)(idx - t * DI);
    float z = xz[t * (2 * DI) + DI + d];
    float y = (ys[idx] + xc[idx] * Dp[d]) * siluf(z);
    ys[idx] = y;
}

// ---------------- launch ----------------
extern "C" void kernel_launch(void* const* d_in, const int* in_sizes, int n_in,
                              void* d_out, int out_size) {
    const float* hidden   = (const float*)d_in[0];
    const float* residual = (const float*)d_in[1];
    const float* norm_w   = (const float*)d_in[2];
    const float* in_proj  = (const float*)d_in[3];   // [8192, 2048]
    const float* conv_w   = (const float*)d_in[4];
    const float* conv_b   = (const float*)d_in[5];
    const float* x_proj   = (const float*)d_in[6];   // [160, 4096]
    const float* dt_proj  = (const float*)d_in[7];   // [4096, 128]
    const float* dt_bias  = (const float*)d_in[8];
    const float* A_log    = (const float*)d_in[9];
    const float* D_param  = (const float*)d_in[10];
    const float* out_proj = (const float*)d_in[11];  // [2048, 4096]

    float* out = (float*)d_out;
    float* resid_out = (out_size >= 2 * T_ * DM) ? out + (size_t)T_ * DM : nullptr;

    // 1) add + rmsnorm
    addnorm_kernel<<<T_, 256>>>(hidden, residual, norm_w, resid_out, g_hs);

    // 2) xz = hs @ in_proj^T : M=2048, N=8192, K=2048
    sgemm2<0, false><<<dim3(2 * DI / 64, T_ / 128, 1), 256>>>(
        g_hs, in_proj, g_xz, T_, 2 * DI, DM, DM, 2 * DI, DM, nullptr);

    // 3) depthwise conv + silu
    conv_silu_kernel<<<dim3(DI / 256, L_ / 64, B_), 256>>>(g_xz, conv_w, conv_b, g_xc);

    // 4) x_dbl partials: M=2048, N=256(padded,160 valid), K=4096, split-K=8
    sgemm2<0, true><<<dim3(NXPAD / 64, T_ / 128, KSPLITS), 256>>>(
        g_xc, x_proj, g_xdblp, T_, NX, DI, DI, NXPAD, DI / KSPLITS, nullptr);
    xdbl_reduce_kernel<<<(T_ * NX + 255) / 256, 256>>>(g_xdblp, g_xdbl);

    // 5) dt = softplus(x_dbl[:, :128] @ dt_proj^T + b) : M=2048, N=4096, K=128
    sgemm2<1, false><<<dim3(DI / 64, T_ / 128, 1), 256>>>(
        g_xdbl, dt_proj, g_dt, T_, DI, NX, DTR, DI, DTR, dt_bias);

    // 6) selective scan
    scan_kernel<<<B_ * DI / 8, 128>>>(g_dt, g_xc, g_xdbl, A_log, g_ys);

    // 7) gate
    gate_kernel<<<(int)(((size_t)T_ * DI) / 256), 256>>>(g_xz, g_xc, D_param, g_ys);

    // 8) out = y @ out_proj^T : M=2048, N=2048, K=4096
    sgemm2<0, false><<<dim3(DM / 64, T_ / 128, 1), 256>>>(
        g_ys, out_proj, out, T_, DM, DI, DI, DM, DI, nullptr);
}

// round 17
// speedup vs baseline: 4.2367x; 1.3375x over previous
#include <cuda_runtime.h>
#include <cuda_bf16.h>
#include <math.h>
#include <stdint.h>

#define B_   2
#define L_   1024
#define DM   2048
#define DI   4096
#define DS   16
#define DTR  128
#define T_   (B_*L_)        // 2048 tokens
#define NX   160            // dt_rank + 2*d_state
#define NXPAD 256
#define KSPLITS 8

// ---------------- scratch (static __device__ arrays; no allocation) ----------------
__device__ float g_hs   [(size_t)T_*DM];
__device__ float g_xz   [(size_t)T_*2*DI];
__device__ float g_xc   [(size_t)T_*DI];
__device__ float g_xdblp[(size_t)KSPLITS*T_*NXPAD];
__device__ float g_xdbl [(size_t)T_*NX];
__device__ float g_dt   [(size_t)T_*DI];
__device__ float g_ys   [(size_t)T_*DI];

// ---------------- helpers ----------------
__device__ __forceinline__ float siluf(float x) { return x / (1.0f + expf(-x)); }
__device__ __forceinline__ float softplusf(float x) { return (x > 20.0f) ? x : log1pf(expf(x)); }

typedef unsigned long long u64;

__device__ __forceinline__ u64 fma2(u64 a, u64 b, u64 c) {
    u64 d;
    asm("fma.rn.f32x2 %0, %1, %2, %3;" : "=l"(d) : "l"(a), "l"(b), "l"(c));
    return d;
}
__device__ __forceinline__ u64 dup2(float x) {
    u64 d;
    asm("mov.b64 %0, {%1, %1};" : "=l"(d) : "f"(x));
    return d;
}
__device__ __forceinline__ float2 unpk(u64 v) {
    float2 f;
    asm("mov.b64 {%0, %1}, %2;" : "=f"(f.x), "=f"(f.y) : "l"(v));
    return f;
}

// ---------------- 1) fused add + RMSNorm ----------------
__global__ void addnorm_kernel(const float* __restrict__ h, const float* __restrict__ r,
                               const float* __restrict__ w, float* __restrict__ resid_out,
                               float* __restrict__ hs) {
    int t = blockIdx.x;
    int tid = threadIdx.x;
    const float* hp = h + (size_t)t * DM;
    const float* rp = r + (size_t)t * DM;
    float v[8];
    float ss = 0.f;
#pragma unroll
    for (int i = 0; i < 8; i++) {
        int c = tid + i * 256;
        float x = hp[c] + rp[c];
        v[i] = x;
        ss += x * x;
    }
    __shared__ float red[256];
    red[tid] = ss;
    __syncthreads();
    for (int s = 128; s > 0; s >>= 1) {
        if (tid < s) red[tid] += red[tid + s];
        __syncthreads();
    }
    float scale = rsqrtf(red[0] / (float)DM + 1e-5f);
#pragma unroll
    for (int i = 0; i < 8; i++) {
        int c = tid + i * 256;
        if (resid_out) resid_out[(size_t)t * DM + c] = v[i];
        hs[(size_t)t * DM + c] = v[i] * scale * w[c];
    }
}

// ---------------- 2) fp32 SGEMM, f32x2 FMA, explicit fragment double-buffer --------
// C[M,N] = A[M,K] * W[N,K]^T. 128x128 CTA tile, BK=8, 256 threads, 8x8/thread.
// Smem double-buffered (1 barrier/stage); smem->reg fragments double-buffered so
// each kk's LDS latency is covered by the previous kk's 32 FFMA2.
template<int EPI, bool NGUARD>
__global__ void __launch_bounds__(256, 2)
sgemm2(const float* __restrict__ A, const float* __restrict__ W, float* __restrict__ C,
       int M, int Nlog, int lda, int ldw, int ldc, int klen,
       const float* __restrict__ bias) {
    __shared__ float As[2][8][132];
    __shared__ float Ws[2][8][132];
    int tid = threadIdx.x;
    int m0 = blockIdx.y * 128, n0 = blockIdx.x * 128;
    int kstart = blockIdx.z * klen;
    float* Cb = C + (size_t)blockIdx.z * M * ldc;

    int r = tid >> 1;            // 0..127
    int k4 = (tid & 1) * 4;      // 0 or 4
    const float* Ag = A + (size_t)(m0 + r) * lda + kstart + k4;
    const float* Wg = W + (size_t)(n0 + r) * ldw + kstart + k4;
    bool wvalid = true;
    if (NGUARD) wvalid = (n0 + r) < Nlog;

    int tx = tid & 15, ty = tid >> 4;

    u64 acc[2][4][4];
#pragma unroll
    for (int rh = 0; rh < 2; rh++)
#pragma unroll
        for (int i = 0; i < 4; i++)
#pragma unroll
            for (int j = 0; j < 4; j++) acc[rh][i][j] = 0ull;

    float4 z4 = make_float4(0.f, 0.f, 0.f, 0.f);
    float4 pa = *(const float4*)Ag;
    float4 pw = wvalid ? *(const float4*)Wg : z4;

    int nst = klen >> 3;

    As[0][k4 + 0][r] = pa.x; As[0][k4 + 1][r] = pa.y;
    As[0][k4 + 2][r] = pa.z; As[0][k4 + 3][r] = pa.w;
    Ws[0][k4 + 0][r] = pw.x; Ws[0][k4 + 1][r] = pw.y;
    Ws[0][k4 + 2][r] = pw.z; Ws[0][k4 + 3][r] = pw.w;
    if (nst > 1) {
        Ag += 8; Wg += 8;
        pa = *(const float4*)Ag;
        pw = wvalid ? *(const float4*)Wg : z4;
    }

    // fragment double buffers (registers)
    float4 a0f[2], a1f[2];
    ulonglong2 b0f[2], b1f[2];

    for (int s = 0; s < nst; s++) {
        int buf = s & 1;
        __syncthreads();
        if (s + 1 < nst) {
            int b2 = buf ^ 1;
            As[b2][k4 + 0][r] = pa.x; As[b2][k4 + 1][r] = pa.y;
            As[b2][k4 + 2][r] = pa.z; As[b2][k4 + 3][r] = pa.w;
            Ws[b2][k4 + 0][r] = pw.x; Ws[b2][k4 + 1][r] = pw.y;
            Ws[b2][k4 + 2][r] = pw.z; Ws[b2][k4 + 3][r] = pw.w;
            if (s + 2 < nst) {
                Ag += 8; Wg += 8;
                pa = *(const float4*)Ag;
                pw = wvalid ? *(const float4*)Wg : z4;
            }
        }
        // preload fragments for kk=0
        a0f[0] = *(const float4*)&As[buf][0][ty * 4];
        a1f[0] = *(const float4*)&As[buf][0][64 + ty * 4];
        b0f[0] = *(const ulonglong2*)&Ws[buf][0][tx * 4];
        b1f[0] = *(const ulonglong2*)&Ws[buf][0][64 + tx * 4];
#pragma unroll
        for (int kk = 0; kk < 8; kk++) {
            int cur = kk & 1, nxt = cur ^ 1;
            if (kk < 7) {
                a0f[nxt] = *(const float4*)&As[buf][kk + 1][ty * 4];
                a1f[nxt] = *(const float4*)&As[buf][kk + 1][64 + ty * 4];
                b0f[nxt] = *(const ulonglong2*)&Ws[buf][kk + 1][tx * 4];
                b1f[nxt] = *(const ulonglong2*)&Ws[buf][kk + 1][64 + tx * 4];
            }
            float4 a0 = a0f[cur], a1 = a1f[cur];
            ulonglong2 b0 = b0f[cur], b1 = b1f[cur];
            u64 d;
            d = dup2(a0.x);
            acc[0][0][0] = fma2(d, b0.x, acc[0][0][0]);
            acc[0][0][1] = fma2(d, b0.y, acc[0][0][1]);
            acc[0][0][2] = fma2(d, b1.x, acc[0][0][2]);
            acc[0][0][3] = fma2(d, b1.y, acc[0][0][3]);
            d = dup2(a0.y);
            acc[0][1][0] = fma2(d, b0.x, acc[0][1][0]);
            acc[0][1][1] = fma2(d, b0.y, acc[0][1][1]);
            acc[0][1][2] = fma2(d, b1.x, acc[0][1][2]);
            acc[0][1][3] = fma2(d, b1.y, acc[0][1][3]);
            d = dup2(a0.z);
            acc[0][2][0] = fma2(d, b0.x, acc[0][2][0]);
            acc[0][2][1] = fma2(d, b0.y, acc[0][2][1]);
            acc[0][2][2] = fma2(d, b1.x, acc[0][2][2]);
            acc[0][2][3] = fma2(d, b1.y, acc[0][2][3]);
            d = dup2(a0.w);
            acc[0][3][0] = fma2(d, b0.x, acc[0][3][0]);
            acc[0][3][1] = fma2(d, b0.y, acc[0][3][1]);
            acc[0][3][2] = fma2(d, b1.x, acc[0][3][2]);
            acc[0][3][3] = fma2(d, b1.y, acc[0][3][3]);
            d = dup2(a1.x);
            acc[1][0][0] = fma2(d, b0.x, acc[1][0][0]);
            acc[1][0][1] = fma2(d, b0.y, acc[1][0][1]);
            acc[1][0][2] = fma2(d, b1.x, acc[1][0][2]);
            acc[1][0][3] = fma2(d, b1.y, acc[1][0][3]);
            d = dup2(a1.y);
            acc[1][1][0] = fma2(d, b0.x, acc[1][1][0]);
            acc[1][1][1] = fma2(d, b0.y, acc[1][1][1]);
            acc[1][1][2] = fma2(d, b1.x, acc[1][1][2]);
            acc[1][1][3] = fma2(d, b1.y, acc[1][1][3]);
            d = dup2(a1.z);
            acc[1][2][0] = fma2(d, b0.x, acc[1][2][0]);
            acc[1][2][1] = fma2(d, b0.y, acc[1][2][1]);
            acc[1][2][2] = fma2(d, b1.x, acc[1][2][2]);
            acc[1][2][3] = fma2(d, b1.y, acc[1][2][3]);
            d = dup2(a1.w);
            acc[1][3][0] = fma2(d, b0.x, acc[1][3][0]);
            acc[1][3][1] = fma2(d, b0.y, acc[1][3][1]);
            acc[1][3][2] = fma2(d, b1.x, acc[1][3][2]);
            acc[1][3][3] = fma2(d, b1.y, acc[1][3][3]);
        }
    }

#pragma unroll
    for (int rh = 0; rh < 2; rh++)
#pragma unroll
        for (int i = 0; i < 4; i++) {
            int row = m0 + rh * 64 + ty * 4 + i;
#pragma unroll
            for (int ch = 0; ch < 2; ch++) {
                int col = n0 + ch * 64 + tx * 4;
                float2 lo = unpk(acc[rh][i][ch * 2 + 0]);
                float2 hi = unpk(acc[rh][i][ch * 2 + 1]);
                float v0 = lo.x, v1 = lo.y, v2 = hi.x, v3 = hi.y;
                if (EPI == 1) {
                    v0 = softplusf(v0 + bias[col + 0]);
                    v1 = softplusf(v1 + bias[col + 1]);
                    v2 = softplusf(v2 + bias[col + 2]);
                    v3 = softplusf(v3 + bias[col + 3]);
                }
                *(float4*)&Cb[(size_t)row * ldc + col] = make_float4(v0, v1, v2, v3);
            }
        }
}

// ---------------- 3) depthwise causal conv (width 4) + SiLU ----------------
__global__ void conv_silu_kernel(const float* __restrict__ xz,
                                 const float* __restrict__ cw,
                                 const float* __restrict__ cb,
                                 float* __restrict__ xc) {
    int d = blockIdx.x * 256 + threadIdx.x;
    int b = blockIdx.z;
    int l0 = blockIdx.y * 64;
    float c0 = cw[d * 4 + 0], c1 = cw[d * 4 + 1], c2 = cw[d * 4 + 2], c3 = cw[d * 4 + 3];
    float bias = cb[d];
    float w0 = 0.f, w1 = 0.f, w2 = 0.f;
#pragma unroll
    for (int j = 3; j >= 1; j--) {
        int l = l0 - j;
        float v = (l >= 0) ? xz[((size_t)(b * L_ + l)) * (2 * DI) + d] : 0.f;
        if (j == 3) w0 = v;
        else if (j == 2) w1 = v;
        else w2 = v;
    }
    for (int i = 0; i < 64; i++) {
        int l = l0 + i;
        float xv = xz[((size_t)(b * L_ + l)) * (2 * DI) + d];
        float a = bias + c0 * w0 + c1 * w1 + c2 * w2 + c3 * xv;
        xc[((size_t)(b * L_ + l)) * DI + d] = siluf(a);
        w0 = w1; w1 = w2; w2 = xv;
    }
}

// ---------------- 4) split-K reduce for x_dbl ----------------
__global__ void xdbl_reduce_kernel(const float* __restrict__ part, float* __restrict__ out) {
    int idx = blockIdx.x * 256 + threadIdx.x;
    if (idx >= T_ * NX) return;
    int t = idx / NX;
    int n = idx - t * NX;
    float s = 0.f;
#pragma unroll
    for (int z = 0; z < KSPLITS; z++)
        s += part[((size_t)z * T_ + t) * NXPAD + n];
    out[idx] = s;
}

// ---------------- 5) selective scan ----------------
__global__ void scan_kernel(const float* __restrict__ dt, const float* __restrict__ xc,
                            const float* __restrict__ xdbl, const float* __restrict__ A_log,
                            float* __restrict__ ys) {
    int tid = threadIdx.x;
    int lane = tid & 15;
    int grp = tid >> 4;
    int ch = blockIdx.x * 8 + grp;
    int b = ch >> 12;
    int d = ch & (DI - 1);
    float Aval = -expf(A_log[d * DS + lane]);
    float h = 0.f;
    size_t baseRow = (size_t)b * L_;
    for (int l = 0; l < L_; l++) {
        size_t t = baseRow + l;
        float dtv = dt[t * DI + d];
        float xv = xc[t * DI + d];
        const float* xd = xdbl + t * NX;
        float bs = xd[DTR + lane];
        float cs = xd[DTR + DS + lane];
        float dA = __expf(dtv * Aval);
        h = fmaf(dA, h, dtv * xv * bs);
        float yp = h * cs;
        yp += __shfl_xor_sync(0xffffffffu, yp, 8);
        yp += __shfl_xor_sync(0xffffffffu, yp, 4);
        yp += __shfl_xor_sync(0xffffffffu, yp, 2);
        yp += __shfl_xor_sync(0xffffffffu, yp, 1);
        if (lane == 0) ys[t * DI + d] = yp;
    }
}

// ---------------- 6) gating: y = (ys + xc*D) * silu(z) ----------------
__global__ void gate_kernel(const float* __restrict__ xz, const float* __restrict__ xc,
                            const float* __restrict__ Dp, float* __restrict__ ys) {
    size_t idx = (size_t)blockIdx.x * 256 + threadIdx.x;
    size_t t = idx / DI;
    int d = (int)(idx - t * DI);
    float z = xz[t * (2 * DI) + DI + d];
    float y = (ys[idx] + xc[idx] * Dp[d]) * siluf(z);
    ys[idx] = y;
}

// ---------------- launch ----------------
extern "C" void kernel_launch(void* const* d_in, const int* in_sizes, int n_in,
                              void* d_out, int out_size) {
    const float* hidden   = (const float*)d_in[0];
    const float* residual = (const float*)d_in[1];
    const float* norm_w   = (const float*)d_in[2];
    const float* in_proj  = (const float*)d_in[3];   // [8192, 2048]
    const float* conv_w   = (const float*)d_in[4];
    const float* conv_b   = (const float*)d_in[5];
    const float* x_proj   = (const float*)d_in[6];   // [160, 4096]
    const float* dt_proj  = (const float*)d_in[7];   // [4096, 128]
    const float* dt_bias  = (const float*)d_in[8];
    const float* A_log    = (const float*)d_in[9];
    const float* D_param  = (const float*)d_in[10];
    const float* out_proj = (const float*)d_in[11];  // [2048, 4096]

    float* out = (float*)d_out;
    float* resid_out = (out_size >= 2 * T_ * DM) ? out + (size_t)T_ * DM : nullptr;

    // 1) add + rmsnorm
    addnorm_kernel<<<T_, 256>>>(hidden, residual, norm_w, resid_out, g_hs);

    // 2) xz = hs @ in_proj^T : M=2048, N=8192, K=2048
    sgemm2<0, false><<<dim3(2 * DI / 128, T_ / 128, 1), 256>>>(
        g_hs, in_proj, g_xz, T_, 2 * DI, DM, DM, 2 * DI, DM, nullptr);

    // 3) depthwise conv + silu
    conv_silu_kernel<<<dim3(DI / 256, L_ / 64, B_), 256>>>(g_xz, conv_w, conv_b, g_xc);

    // 4) x_dbl partials: M=2048, N=256(padded,160 valid), K=4096, split-K=8
    sgemm2<0, true><<<dim3(NXPAD / 128, T_ / 128, KSPLITS), 256>>>(
        g_xc, x_proj, g_xdblp, T_, NX, DI, DI, NXPAD, DI / KSPLITS, nullptr);
    xdbl_reduce_kernel<<<(T_ * NX + 255) / 256, 256>>>(g_xdblp, g_xdbl);

    // 5) dt = softplus(x_dbl[:, :128] @ dt_proj^T + b) : M=2048, N=4096, K=128
    sgemm2<1, false><<<dim3(DI / 128, T_ / 128, 1), 256>>>(
        g_xdbl, dt_proj, g_dt, T_, DI, NX, DTR, DI, DTR, dt_bias);

    // 6) selective scan
    scan_kernel<<<B_ * DI / 8, 128>>>(g_dt, g_xc, g_xdbl, A_log, g_ys);

    // 7) gate
    gate_kernel<<<(int)(((size_t)T_ * DI) / 256), 256>>>(g_xz, g_xc, D_param, g_ys);

    // 8) out = y @ out_proj^T : M=2048, N=2048, K=4096
    sgemm2<0, false><<<dim3(DM / 128, T_ / 128, 1), 256>>>(
        g_ys, out_proj, out, T_, DM, DI, DI, DM, DI, nullptr);
}